// round 10
// baseline (speedup 1.0000x reference)
#include <cuda_runtime.h>
#include <cuda_fp16.h>
#include <cstdint>

// GruLayer: B=64, T=512, D_in=L=1024.
// Prep: X -> fp16 g_Xh; weights -> fp16 transposed g_Bt (x-proj) / g_Br (recurrent).
// Phase A (fp16 HMMA, 128x256 tile, ldmatrix, 3-stage cp.async, 1 sync/tile):
//   XG = x @ [w_W_top | wx_W] + bias
// Phase B (persistent dataflow, 64 blocks x 16 cols, producer flags instead of
//   a global barrier): G = h_{t-1} @ [w_W_bot | wh_W]
//   hs=sig(G1+XG1); os=sig(G2+XG2); h_t = os*h + (1-os)*tanh(XGm + hs*(Gm+wh_b))

__device__ float  g_XG[(size_t)32768 * 3072];   // [t*64+b][3072] scratch (~403 MB)
__device__ __half g_Xh[(size_t)32768 * 1024];   // X fp16 (64 MB)
__device__ __half g_Bt[(size_t)3072 * 1024];    // [n][k] fp16 x-proj weights
__device__ __half g_Br[(size_t)3072 * 1024];    // [n][k] fp16 recurrent weights
__device__ __half g_h[2 * 64 * 1024];           // fp16 h ping-pong
__device__ int      g_pflag[64];                // producer publish flags
__device__ unsigned g_staged;                   // staging-completion counter

__device__ __forceinline__ void mma_f16(float* c,
                                        uint32_t a0, uint32_t a1, uint32_t a2, uint32_t a3,
                                        uint32_t b0, uint32_t b1) {
    asm volatile(
        "mma.sync.aligned.m16n8k16.row.col.f32.f16.f16.f32 "
        "{%0,%1,%2,%3},{%4,%5,%6,%7},{%8,%9},{%0,%1,%2,%3};"
        : "+f"(c[0]), "+f"(c[1]), "+f"(c[2]), "+f"(c[3])
        : "r"(a0), "r"(a1), "r"(a2), "r"(a3), "r"(b0), "r"(b1));
}

__device__ __forceinline__ void ldsm_x4(uint32_t& r0, uint32_t& r1,
                                        uint32_t& r2, uint32_t& r3,
                                        const void* p) {
    uint32_t a = (uint32_t)__cvta_generic_to_shared(p);
    asm volatile("ldmatrix.sync.aligned.m8n8.x4.shared.b16 {%0,%1,%2,%3}, [%4];"
                 : "=r"(r0), "=r"(r1), "=r"(r2), "=r"(r3) : "r"(a));
}

__device__ __forceinline__ void cp_async16(void* smem, const void* gmem) {
    uint32_t s = (uint32_t)__cvta_generic_to_shared(smem);
    asm volatile("cp.async.cg.shared.global [%0], [%1], 16;" :: "r"(s), "l"(gmem));
}
__device__ __forceinline__ void cp_commit() {
    asm volatile("cp.async.commit_group;");
}
template <int N>
__device__ __forceinline__ void cp_wait() {
    asm volatile("cp.async.wait_group %0;" :: "n"(N));
}

__device__ __forceinline__ int ld_acquire(const int* p) {
    int v;
    asm volatile("ld.global.acquire.gpu.s32 %0, [%1];" : "=r"(v) : "l"(p));
    return v;
}
__device__ __forceinline__ unsigned ld_acquire_u(const unsigned* p) {
    unsigned v;
    asm volatile("ld.global.acquire.gpu.u32 %0, [%1];" : "=r"(v) : "l"(p));
    return v;
}

// ---------------------------------------------------------------------------
// Prep 1: X fp32 -> fp16
// ---------------------------------------------------------------------------
__global__ __launch_bounds__(256) void prep_x_kernel(const float* __restrict__ x) {
    size_t i = ((size_t)blockIdx.x * 256 + threadIdx.x) * 8;
    float4 v0 = *reinterpret_cast<const float4*>(x + i);
    float4 v1 = *reinterpret_cast<const float4*>(x + i + 4);
    __half2 h0 = __floats2half2_rn(v0.x, v0.y);
    __half2 h1 = __floats2half2_rn(v0.z, v0.w);
    __half2 h2 = __floats2half2_rn(v1.x, v1.y);
    __half2 h3 = __floats2half2_rn(v1.z, v1.w);
    uint4 o;
    o.x = *(uint32_t*)&h0; o.y = *(uint32_t*)&h1;
    o.z = *(uint32_t*)&h2; o.w = *(uint32_t*)&h3;
    *reinterpret_cast<uint4*>(g_Xh + i) = o;
}

// ---------------------------------------------------------------------------
// Prep 2: weights -> fp16, transposed to [n][k]. z=0 -> g_Bt, z=1 -> g_Br.
// ---------------------------------------------------------------------------
__global__ __launch_bounds__(256) void prep_w_kernel(
    const float* __restrict__ wW,    // [2048,2048]
    const float* __restrict__ wxW,   // [1024,1024]
    const float* __restrict__ whW)   // [1024,1024]
{
    __shared__ float tile[32][33];
    const int n0 = blockIdx.x * 32, k0 = blockIdx.y * 32;
    const int which = blockIdx.z;
    const int tx = threadIdx.x, ty = threadIdx.y;   // 32 x 8

    for (int i = ty; i < 32; i += 8) {
        int k = k0 + i, n = n0 + tx;
        float v;
        if (which == 0) v = (n < 2048) ? wW[(size_t)k * 2048 + n]
                                       : wxW[(size_t)k * 1024 + (n - 2048)];
        else            v = (n < 2048) ? wW[(size_t)(1024 + k) * 2048 + n]
                                       : whW[(size_t)k * 1024 + (n - 2048)];
        tile[i][tx] = v;
    }
    __syncthreads();
    __half* dst = which ? g_Br : g_Bt;
    for (int i = ty; i < 32; i += 8) {
        int n = n0 + i, k = k0 + tx;
        dst[(size_t)n * 1024 + k] = __float2half_rn(tile[tx][i]);
    }
}

// ---------------------------------------------------------------------------
// Init: h0 -> fp16 ping buffer 0, reset flags/counters.
// ---------------------------------------------------------------------------
__global__ void initB_kernel(const float* __restrict__ h0) {
    int i = blockIdx.x * 256 + threadIdx.x;   // 65536 threads
    g_h[i] = __float2half_rn(h0[i]);
    if (i < 64) g_pflag[i] = 0;
    if (i == 0) g_staged = 0;
}

// ---------------------------------------------------------------------------
// Phase A: C[32768,3072] = Xh @ Bt^T + bias, fp16 HMMA + ldmatrix.
// Block tile 128m x 256n, 512 threads (16 warps, warp tile 32x64), k-step 32,
// 3-stage cp.async pipeline, single __syncthreads per k-tile (MMA-then-load).
// ---------------------------------------------------------------------------
#define PA2_ST 40                       // halves per smem row
#define PA2_A_HALVES (128 * PA2_ST)     // 5120
#define PA2_STAGE (384 * PA2_ST)        // 15360 halves per stage (A + B)

__global__ __launch_bounds__(512, 1) void phaseA_kernel(
    const float* __restrict__ wb,    // [2048]
    const float* __restrict__ wxb)   // [1024]
{
    extern __shared__ __align__(16) __half paSmem[];

    const int tid  = threadIdx.x;
    const int warp = tid >> 5, lane = tid & 31;
    const int gID  = lane >> 2, tig = lane & 3;
    const int wm   = warp & 3, wn = warp >> 2;     // 4m x 4n warp grid
    const int row0 = blockIdx.y * 128;
    const int j0   = blockIdx.x * 256;

    const int a_row  = lane & 15;
    const int a_koff = (lane >> 4) << 3;
    const int b_row  = (lane & 7) | ((lane >> 4) << 3);
    const int b_koff = ((lane >> 3) & 1) << 3;

    auto load_tile = [&](int buf, int kt) {
        __half* Ah = paSmem + buf * PA2_STAGE;
        __half* Bh = Ah + PA2_A_HALVES;
#pragma unroll
        for (int i = tid; i < 1536; i += 512) {
            int row = i >> 2, c = i & 3;           // 16B chunk index
            if (row < 128)
                cp_async16(Ah + row * PA2_ST + c * 8,
                           g_Xh + (size_t)(row0 + row) * 1024 + kt + c * 8);
            else
                cp_async16(Bh + (row - 128) * PA2_ST + c * 8,
                           g_Bt + (size_t)(j0 + row - 128) * 1024 + kt + c * 8);
        }
    };

    float acc[2][8][4];
#pragma unroll
    for (int mi = 0; mi < 2; mi++)
#pragma unroll
        for (int ni = 0; ni < 8; ni++)
#pragma unroll
            for (int i = 0; i < 4; i++) acc[mi][ni][i] = 0.f;

    load_tile(0, 0);  cp_commit();
    load_tile(1, 32); cp_commit();

    for (int it = 0; it < 32; it++) {
        int buf = it % 3;
        cp_wait<1>();          // tile `it` complete (1 newer group may be pending)
        __syncthreads();

        const __half* Ah = paSmem + buf * PA2_STAGE;
        const __half* Bh = Ah + PA2_A_HALVES;

#pragma unroll
        for (int ki = 0; ki < 2; ki++) {
            int kb = ki * 16;
            uint32_t a[2][4];
#pragma unroll
            for (int mi = 0; mi < 2; mi++)
                ldsm_x4(a[mi][0], a[mi][1], a[mi][2], a[mi][3],
                        Ah + (wm * 32 + mi * 16 + a_row) * PA2_ST + kb + a_koff);
#pragma unroll
            for (int nj = 0; nj < 4; nj++) {
                uint32_t r0, r1, r2, r3;
                ldsm_x4(r0, r1, r2, r3,
                        Bh + (wn * 64 + nj * 16 + b_row) * PA2_ST + kb + b_koff);
#pragma unroll
                for (int mi = 0; mi < 2; mi++) {
                    mma_f16(acc[mi][nj * 2],     a[mi][0], a[mi][1], a[mi][2], a[mi][3], r0, r1);
                    mma_f16(acc[mi][nj * 2 + 1], a[mi][0], a[mi][1], a[mi][2], a[mi][3], r2, r3);
                }
            }
        }

        if (it + 2 < 32) load_tile((it + 2) % 3, (it + 2) * 32);
        cp_commit();           // empty group at tail keeps accounting aligned
    }

    // epilogue: bias + permuted fp32 store to g_XG ([t][b] row order)
    float bv[8][2];
#pragma unroll
    for (int ni = 0; ni < 8; ni++) {
        int col = j0 + wn * 64 + ni * 8 + tig * 2;
        if (col < 2048) { bv[ni][0] = wb[col];         bv[ni][1] = wb[col + 1]; }
        else            { bv[ni][0] = wxb[col - 2048]; bv[ni][1] = wxb[col - 2047]; }
    }
#pragma unroll
    for (int mi = 0; mi < 2; mi++) {
#pragma unroll
        for (int h = 0; h < 2; h++) {
            int grow = row0 + wm * 32 + mi * 16 + gID + h * 8;  // (b*512 + t)
            int bb = grow >> 9, tt = grow & 511;
            size_t orow = (size_t)(tt * 64 + bb) * 3072;
#pragma unroll
            for (int ni = 0; ni < 8; ni++) {
                int col = j0 + wn * 64 + ni * 8 + tig * 2;
                g_XG[orow + col]     = acc[mi][ni][h * 2]     + bv[ni][0];
                g_XG[orow + col + 1] = acc[mi][ni][h * 2 + 1] + bv[ni][1];
            }
        }
    }
}

// ---------------------------------------------------------------------------
// Phase B: persistent dataflow kernel. 64 blocks x 256 threads (8 warps).
// Block = 16-column tile of latent dim (all 3 weight groups in smem fp16).
// Warp w owns k-halves [128w, 128w+128) for ALL 64 rows and 6 B-fragments.
// No global barrier: block b publishes pflag[b]=t+1 after writing its 16
// columns of h_t; consumer warp w polls only its 8 producers (4 per 8KB
// staging chunk). g_staged (1 atomicAdd/block/step) gates ping-pong reuse
// with a full step of slack. Partials reduced via smem overlay on Hs.
// ---------------------------------------------------------------------------
#define PB_ST 1032   // halves per smem row (conflict-free ldmatrix)

__global__ __launch_bounds__(256) void phaseB_kernel(
    const float* __restrict__ h0,
    const float* __restrict__ whb,    // [1024]
    float* __restrict__ out)          // [64,512,1024]
{
    extern __shared__ __align__(16) __half smem[];
    __half* Wt = smem;                   // [48][1032]  (g*16+col rows)
    __half* Hs = smem + 48 * PB_ST;      // [64][1032]  (Red overlays after MMA)
    float*  Red = reinterpret_cast<float*>(Hs);   // [src8][mt4][f6][lane32][4]

    const int tid  = threadIdx.x;
    const int warp = tid >> 5, lane = tid & 31;
    const int gID  = lane >> 2, tig = lane & 3;
    const int mt   = warp & 3;           // m-tile this warp reduces/outputs
    const int nf   = warp >> 2;          // n-fragment (0/1) for epilogue
    const int jt   = blockIdx.x * 16;
    const int jcol0 = jt + nf * 8 + tig * 2;
    const int kh   = warp * 128;         // half offset of this warp's k-slice

    const int a_row  = lane & 15;
    const int a_koff = (lane >> 4) << 3;
    const int b_row  = (lane & 7) | ((lane >> 4) << 3);
    const int b_koff = ((lane >> 3) & 1) << 3;

    // one-time: weights from g_Br ([n][k] fp16) -> smem rows g*16+col
    for (int idx = tid; idx < 48 * 128; idx += 256) {
        int row = idx >> 7, c = idx & 127;
        int g = row >> 4, col = row & 15;
        uint4 v = *reinterpret_cast<const uint4*>(
            g_Br + (size_t)(g * 1024 + jt + col) * 1024 + c * 8);
        *reinterpret_cast<uint4*>(Wt + (size_t)row * PB_ST + c * 8) = v;
    }
    const float bwh0 = whb[jcol0];
    const float bwh1 = whb[jcol0 + 1];

    // register-carried h_prev for this thread's 4 output slots
    float hpv[2][2];
#pragma unroll
    for (int h = 0; h < 2; h++) {
        int r = mt * 16 + gID + h * 8;
        hpv[h][0] = h0[(size_t)r * 1024 + jcol0];
        hpv[h][1] = h0[(size_t)r * 1024 + jcol0 + 1];
    }
    // XG prefetch for t=0
    float xg[2][2][3];
#pragma unroll
    for (int h = 0; h < 2; h++) {
        int r = mt * 16 + gID + h * 8;
        const float* xr = g_XG + (size_t)r * 3072 + jcol0;
#pragma unroll
        for (int cc = 0; cc < 2; cc++) {
            xg[h][cc][0] = xr[cc];
            xg[h][cc][1] = xr[1024 + cc];
            xg[h][cc][2] = xr[2048 + cc];
        }
    }
    __syncthreads();

    for (int t = 0; t < 512; t++) {
        const __half* hsrc = g_h + (size_t)(t & 1) * 65536;
        __half*       hdst = g_h + (size_t)((t + 1) & 1) * 65536;

        // ---- chunk 0: poll 4 producers, stage k-halves [kh, kh+64)
        if (lane < 4) {
            const int* fp = g_pflag + 8 * warp + lane;
            while (ld_acquire(fp) < t) { }
        }
        __syncwarp();
#pragma unroll
        for (int i = lane; i < 512; i += 32) {
            int r = i >> 3, c = i & 7;
            cp_async16(Hs + (size_t)r * PB_ST + kh + c * 8,
                       hsrc + (size_t)r * 1024 + kh + c * 8);
        }
        cp_commit();
        // ---- chunk 1: poll next 4 producers, stage [kh+64, kh+128)
        if (lane < 4) {
            const int* fp = g_pflag + 8 * warp + 4 + lane;
            while (ld_acquire(fp) < t) { }
        }
        __syncwarp();
#pragma unroll
        for (int i = lane; i < 512; i += 32) {
            int r = i >> 3, c = i & 7;
            cp_async16(Hs + (size_t)r * PB_ST + kh + 64 + c * 8,
                       hsrc + (size_t)r * 1024 + kh + 64 + c * 8);
        }
        cp_commit();

        // ---- MMA over this warp's k-slice: 4 mt x 6 frags x 8 k-steps
        float acc[4][6][4];
#pragma unroll
        for (int m2 = 0; m2 < 4; m2++)
#pragma unroll
            for (int f = 0; f < 6; f++)
#pragma unroll
                for (int i = 0; i < 4; i++) acc[m2][f][i] = 0.f;

        auto do4 = [&](int q) {
#pragma unroll
            for (int kk = 0; kk < 4; kk++) {
                int kbase = kh + (q * 4 + kk) * 16;
                uint32_t a[4][4];
#pragma unroll
                for (int m2 = 0; m2 < 4; m2++)
                    ldsm_x4(a[m2][0], a[m2][1], a[m2][2], a[m2][3],
                            Hs + (m2 * 16 + a_row) * PB_ST + kbase + a_koff);
#pragma unroll
                for (int g = 0; g < 3; g++) {
                    uint32_t r0, r1, r2, r3;
                    ldsm_x4(r0, r1, r2, r3,
                            Wt + (g * 16 + b_row) * PB_ST + kbase + b_koff);
#pragma unroll
                    for (int m2 = 0; m2 < 4; m2++) {
                        mma_f16(acc[m2][g * 2],     a[m2][0], a[m2][1], a[m2][2], a[m2][3], r0, r1);
                        mma_f16(acc[m2][g * 2 + 1], a[m2][0], a[m2][1], a[m2][2], a[m2][3], r2, r3);
                    }
                }
            }
        };
        cp_wait<1>(); __syncwarp(); do4(0);
        cp_wait<0>(); __syncwarp(); do4(1);

        __syncthreads();                       // all warps done reading Hs
        if (tid == 0) atomicAdd(&g_staged, 1u);

        // ---- partial store (Red overlays Hs)
#pragma unroll
        for (int m2 = 0; m2 < 4; m2++)
#pragma unroll
            for (int f = 0; f < 6; f++) {
                int idx = (((warp * 4 + m2) * 6 + f) * 32 + lane) * 4;
                *reinterpret_cast<float4*>(Red + idx) =
                    make_float4(acc[m2][f][0], acc[m2][f][1], acc[m2][f][2], acc[m2][f][3]);
            }
        __syncthreads();

        // ---- reduce: warp owns (mt, nf) -> frags f = g*2+nf, g=0..2
        float facc[3][4];
#pragma unroll
        for (int g = 0; g < 3; g++)
#pragma unroll
            for (int c = 0; c < 4; c++) facc[g][c] = 0.f;
#pragma unroll
        for (int src = 0; src < 8; src++)
#pragma unroll
            for (int g = 0; g < 3; g++) {
                float4 v = *reinterpret_cast<const float4*>(
                    Red + (((src * 4 + mt) * 6 + g * 2 + nf) * 32 + lane) * 4);
                facc[g][0] += v.x; facc[g][1] += v.y;
                facc[g][2] += v.z; facc[g][3] += v.w;
            }

        // ---- ping-pong write safety: all blocks staged step t-1 (slack ~1 step)
        if (tid == 0 && t > 0) {
            unsigned target = (unsigned)t * 64u;
            while (ld_acquire_u(&g_staged) < target) { }
        }
        __syncthreads();                       // Red consumed; safety confirmed

        // ---- fused nonlinearity + stores
#pragma unroll
        for (int h = 0; h < 2; h++) {
            int r = mt * 16 + gID + h * 8;
            float hn[2];
#pragma unroll
            for (int cc = 0; cc < 2; cc++) {
                float g1 = facc[0][h * 2 + cc] + xg[h][cc][0];
                float g2 = facc[1][h * 2 + cc] + xg[h][cc][1];
                float hm = facc[2][h * 2 + cc] + ((cc == 0) ? bwh0 : bwh1);
                float xm = xg[h][cc][2];
                float hs = 1.f / (1.f + __expf(-g1));
                float os = 1.f / (1.f + __expf(-g2));
                float mm = xm + hs * hm;
                hn[cc] = os * hpv[h][cc] + (1.f - os) * tanhf(mm);
                out[((size_t)r * 512 + t) * 1024 + jcol0 + cc] = hn[cc];
                hpv[h][cc] = hn[cc];
            }
            *(reinterpret_cast<__half2*>(hdst + (size_t)r * 1024 + jcol0)) =
                __floats2half2_rn(hn[0], hn[1]);
        }

        // ---- XG prefetch for t+1 (hidden behind publish/poll of next step)
        if (t + 1 < 512) {
            size_t xb = (size_t)(t + 1) * 64 * 3072;
#pragma unroll
            for (int h = 0; h < 2; h++) {
                int r = mt * 16 + gID + h * 8;
                const float* xr = g_XG + xb + (size_t)r * 3072 + jcol0;
#pragma unroll
                for (int cc = 0; cc < 2; cc++) {
                    xg[h][cc][0] = xr[cc];
                    xg[h][cc][1] = xr[1024 + cc];
                    xg[h][cc][2] = xr[2048 + cc];
                }
            }
        }

        // ---- publish this block's 16 columns of h_t
        __threadfence();
        __syncthreads();
        if (tid == 0) atomicExch(&g_pflag[blockIdx.x], t + 1);
    }
}

extern "C" void kernel_launch(void* const* d_in, const int* in_sizes, int n_in,
                              void* d_out, int out_size) {
    const float* x   = (const float*)d_in[0];
    const float* h0  = (const float*)d_in[1];
    const float* wW  = (const float*)d_in[2];
    const float* wb  = (const float*)d_in[3];
    const float* wxW = (const float*)d_in[4];
    const float* wxb = (const float*)d_in[5];
    const float* whW = (const float*)d_in[6];
    const float* whb = (const float*)d_in[7];
    float* out = (float*)d_out;

    const int smemA = 3 * PA2_STAGE * (int)sizeof(__half);           // 92160 B
    const int smemB = (48 + 64) * PB_ST * (int)sizeof(__half);       // 231168 B
    cudaFuncSetAttribute(phaseA_kernel,
                         cudaFuncAttributeMaxDynamicSharedMemorySize, smemA);
    cudaFuncSetAttribute(phaseB_kernel,
                         cudaFuncAttributeMaxDynamicSharedMemorySize, smemB);

    prep_x_kernel<<<16384, 256>>>(x);
    prep_w_kernel<<<dim3(96, 32, 2), dim3(32, 8)>>>(wW, wxW, whW);
    initB_kernel<<<256, 256>>>(h0);
    phaseA_kernel<<<dim3(12, 256), 512, smemA>>>(wb, wxb);
    phaseB_kernel<<<64, 256, smemB>>>(h0, whb, out);
}

// round 11
// speedup vs baseline: 1.1389x; 1.1389x over previous
#include <cuda_runtime.h>
#include <cuda_fp16.h>
#include <cstdint>

// GruLayer: B=64, T=512, D_in=L=1024.
// Prep: X -> fp16 g_Xh; weights -> fp16 transposed g_Bt (x-proj) / g_Br (recurrent).
// Phase A (fp16 HMMA, 128x256 tile, ldmatrix, 3-stage cp.async, 1 sync/tile):
//   XG = x @ [w_W_top | wx_W] + bias
// Phase B (persistent, 128 blocks, global barrier per step, k-split warps,
//   chunked per-warp h staging, ldmatrix A-fragments):
//   G = h_{t-1} @ [w_W_bot | wh_W]; hs=sig(G1+XG1); os=sig(G2+XG2)
//   h_t = os*h + (1-os)*tanh(XGm + hs*(Gm + wh_b))

__device__ float  g_XG[(size_t)32768 * 3072];   // [t*64+b][3072] scratch (~403 MB)
__device__ __half g_Xh[(size_t)32768 * 1024];   // X fp16 (64 MB)
__device__ __half g_Bt[(size_t)3072 * 1024];    // [n][k] fp16 x-proj weights
__device__ __half g_Br[(size_t)3072 * 1024];    // [n][k] fp16 recurrent weights
__device__ __half g_h[2 * 64 * 1024];           // fp16 h ping-pong
__device__ unsigned g_arrive;                   // grid barrier counter

__device__ __forceinline__ void mma_f16(float* c,
                                        uint32_t a0, uint32_t a1, uint32_t a2, uint32_t a3,
                                        uint32_t b0, uint32_t b1) {
    asm volatile(
        "mma.sync.aligned.m16n8k16.row.col.f32.f16.f16.f32 "
        "{%0,%1,%2,%3},{%4,%5,%6,%7},{%8,%9},{%0,%1,%2,%3};"
        : "+f"(c[0]), "+f"(c[1]), "+f"(c[2]), "+f"(c[3])
        : "r"(a0), "r"(a1), "r"(a2), "r"(a3), "r"(b0), "r"(b1));
}

__device__ __forceinline__ void ldsm_x4(uint32_t& r0, uint32_t& r1,
                                        uint32_t& r2, uint32_t& r3,
                                        const void* p) {
    uint32_t a = (uint32_t)__cvta_generic_to_shared(p);
    asm volatile("ldmatrix.sync.aligned.m8n8.x4.shared.b16 {%0,%1,%2,%3}, [%4];"
                 : "=r"(r0), "=r"(r1), "=r"(r2), "=r"(r3) : "r"(a));
}

__device__ __forceinline__ void cp_async16(void* smem, const void* gmem) {
    uint32_t s = (uint32_t)__cvta_generic_to_shared(smem);
    asm volatile("cp.async.cg.shared.global [%0], [%1], 16;" :: "r"(s), "l"(gmem));
}
__device__ __forceinline__ void cp_commit() {
    asm volatile("cp.async.commit_group;");
}
template <int N>
__device__ __forceinline__ void cp_wait() {
    asm volatile("cp.async.wait_group %0;" :: "n"(N));
}

// ---------------------------------------------------------------------------
// Prep 1: X fp32 -> fp16
// ---------------------------------------------------------------------------
__global__ __launch_bounds__(256) void prep_x_kernel(const float* __restrict__ x) {
    size_t i = ((size_t)blockIdx.x * 256 + threadIdx.x) * 8;
    float4 v0 = *reinterpret_cast<const float4*>(x + i);
    float4 v1 = *reinterpret_cast<const float4*>(x + i + 4);
    __half2 h0 = __floats2half2_rn(v0.x, v0.y);
    __half2 h1 = __floats2half2_rn(v0.z, v0.w);
    __half2 h2 = __floats2half2_rn(v1.x, v1.y);
    __half2 h3 = __floats2half2_rn(v1.z, v1.w);
    uint4 o;
    o.x = *(uint32_t*)&h0; o.y = *(uint32_t*)&h1;
    o.z = *(uint32_t*)&h2; o.w = *(uint32_t*)&h3;
    *reinterpret_cast<uint4*>(g_Xh + i) = o;
}

// ---------------------------------------------------------------------------
// Prep 2: weights -> fp16, transposed to [n][k]. z=0 -> g_Bt, z=1 -> g_Br.
// ---------------------------------------------------------------------------
__global__ __launch_bounds__(256) void prep_w_kernel(
    const float* __restrict__ wW,    // [2048,2048]
    const float* __restrict__ wxW,   // [1024,1024]
    const float* __restrict__ whW)   // [1024,1024]
{
    __shared__ float tile[32][33];
    const int n0 = blockIdx.x * 32, k0 = blockIdx.y * 32;
    const int which = blockIdx.z;
    const int tx = threadIdx.x, ty = threadIdx.y;   // 32 x 8

    for (int i = ty; i < 32; i += 8) {
        int k = k0 + i, n = n0 + tx;
        float v;
        if (which == 0) v = (n < 2048) ? wW[(size_t)k * 2048 + n]
                                       : wxW[(size_t)k * 1024 + (n - 2048)];
        else            v = (n < 2048) ? wW[(size_t)(1024 + k) * 2048 + n]
                                       : whW[(size_t)k * 1024 + (n - 2048)];
        tile[i][tx] = v;
    }
    __syncthreads();
    __half* dst = which ? g_Br : g_Bt;
    for (int i = ty; i < 32; i += 8) {
        int n = n0 + i, k = k0 + tx;
        dst[(size_t)n * 1024 + k] = __float2half_rn(tile[tx][i]);
    }
}

// ---------------------------------------------------------------------------
// Init: h0 -> fp16 ping buffer 0, reset grid-barrier counter.
// ---------------------------------------------------------------------------
__global__ void initB_kernel(const float* __restrict__ h0) {
    int i = blockIdx.x * 256 + threadIdx.x;   // 65536 threads
    g_h[i] = __float2half_rn(h0[i]);
    if (i == 0) g_arrive = 0;
}

// ---------------------------------------------------------------------------
// Phase A: C[32768,3072] = Xh @ Bt^T + bias, fp16 HMMA + ldmatrix.
// Block tile 128m x 256n, 512 threads (16 warps, warp tile 32x64), k-step 32,
// 3-stage cp.async pipeline, single __syncthreads per k-tile (MMA-then-load).
// ---------------------------------------------------------------------------
#define PA2_ST 40                       // halves per smem row
#define PA2_A_HALVES (128 * PA2_ST)     // 5120
#define PA2_STAGE (384 * PA2_ST)        // 15360 halves per stage (A + B)

__global__ __launch_bounds__(512, 1) void phaseA_kernel(
    const float* __restrict__ wb,    // [2048]
    const float* __restrict__ wxb)   // [1024]
{
    extern __shared__ __align__(16) __half paSmem[];

    const int tid  = threadIdx.x;
    const int warp = tid >> 5, lane = tid & 31;
    const int gID  = lane >> 2, tig = lane & 3;
    const int wm   = warp & 3, wn = warp >> 2;     // 4m x 4n warp grid
    const int row0 = blockIdx.y * 128;
    const int j0   = blockIdx.x * 256;

    const int a_row  = lane & 15;
    const int a_koff = (lane >> 4) << 3;
    const int b_row  = (lane & 7) | ((lane >> 4) << 3);
    const int b_koff = ((lane >> 3) & 1) << 3;

    auto load_tile = [&](int buf, int kt) {
        __half* Ah = paSmem + buf * PA2_STAGE;
        __half* Bh = Ah + PA2_A_HALVES;
#pragma unroll
        for (int i = tid; i < 1536; i += 512) {
            int row = i >> 2, c = i & 3;           // 16B chunk index
            if (row < 128)
                cp_async16(Ah + row * PA2_ST + c * 8,
                           g_Xh + (size_t)(row0 + row) * 1024 + kt + c * 8);
            else
                cp_async16(Bh + (row - 128) * PA2_ST + c * 8,
                           g_Bt + (size_t)(j0 + row - 128) * 1024 + kt + c * 8);
        }
    };

    float acc[2][8][4];
#pragma unroll
    for (int mi = 0; mi < 2; mi++)
#pragma unroll
        for (int ni = 0; ni < 8; ni++)
#pragma unroll
            for (int i = 0; i < 4; i++) acc[mi][ni][i] = 0.f;

    load_tile(0, 0);  cp_commit();
    load_tile(1, 32); cp_commit();

    for (int it = 0; it < 32; it++) {
        int buf = it % 3;
        cp_wait<1>();          // tile `it` complete
        __syncthreads();

        const __half* Ah = paSmem + buf * PA2_STAGE;
        const __half* Bh = Ah + PA2_A_HALVES;

#pragma unroll
        for (int ki = 0; ki < 2; ki++) {
            int kb = ki * 16;
            uint32_t a[2][4];
#pragma unroll
            for (int mi = 0; mi < 2; mi++)
                ldsm_x4(a[mi][0], a[mi][1], a[mi][2], a[mi][3],
                        Ah + (wm * 32 + mi * 16 + a_row) * PA2_ST + kb + a_koff);
#pragma unroll
            for (int nj = 0; nj < 4; nj++) {
                uint32_t r0, r1, r2, r3;
                ldsm_x4(r0, r1, r2, r3,
                        Bh + (wn * 64 + nj * 16 + b_row) * PA2_ST + kb + b_koff);
#pragma unroll
                for (int mi = 0; mi < 2; mi++) {
                    mma_f16(acc[mi][nj * 2],     a[mi][0], a[mi][1], a[mi][2], a[mi][3], r0, r1);
                    mma_f16(acc[mi][nj * 2 + 1], a[mi][0], a[mi][1], a[mi][2], a[mi][3], r2, r3);
                }
            }
        }

        if (it + 2 < 32) load_tile((it + 2) % 3, (it + 2) * 32);
        cp_commit();           // empty group at tail keeps accounting aligned
    }

    // epilogue: bias + permuted fp32 store to g_XG ([t][b] row order)
    float bv[8][2];
#pragma unroll
    for (int ni = 0; ni < 8; ni++) {
        int col = j0 + wn * 64 + ni * 8 + tig * 2;
        if (col < 2048) { bv[ni][0] = wb[col];         bv[ni][1] = wb[col + 1]; }
        else            { bv[ni][0] = wxb[col - 2048]; bv[ni][1] = wxb[col - 2047]; }
    }
#pragma unroll
    for (int mi = 0; mi < 2; mi++) {
#pragma unroll
        for (int h = 0; h < 2; h++) {
            int grow = row0 + wm * 32 + mi * 16 + gID + h * 8;  // (b*512 + t)
            int bb = grow >> 9, tt = grow & 511;
            size_t orow = (size_t)(tt * 64 + bb) * 3072;
#pragma unroll
            for (int ni = 0; ni < 8; ni++) {
                int col = j0 + wn * 64 + ni * 8 + tig * 2;
                g_XG[orow + col]     = acc[mi][ni][h * 2]     + bv[ni][0];
                g_XG[orow + col + 1] = acc[mi][ni][h * 2 + 1] + bv[ni][1];
            }
        }
    }
}

// ---------------------------------------------------------------------------
// Phase B: persistent kernel. 128 blocks x 128 threads (4 warps), co-resident.
// Block = 8-column tile of latent dim; weights cached in smem fp16.
// Warps are K-SPLIT (warp w owns k in [256w,256w+256) halves for all 64 rows,
// all 3 groups). h staging is per-warp and chunked (4 groups of 8KB) with MMA
// overlap. A-fragments via ldmatrix.x4 (4 LDSM vs 16 LDS per k16). Partials
// reduced via smem overlay; h_prev register-carried; XG for t+1 prefetched
// before the grid barrier.
// ---------------------------------------------------------------------------
#define SMEM_W_STRIDE 1032   // halves per weight column (conflict-free)
#define SMEM_H_STRIDE 1032   // halves per h row

__global__ __launch_bounds__(128) void phaseB_kernel(
    const float* __restrict__ h0,
    const float* __restrict__ whb,    // [1024]
    float* __restrict__ out)          // [64,512,1024]
{
    extern __shared__ __align__(16) __half smem[];
    __half* Wt = smem;                               // [3*8][1032]
    __half* Hs = smem + 3 * 8 * SMEM_W_STRIDE;       // [64][1032]  (Red overlays)

    const int tid  = threadIdx.x;
    const int warp = tid >> 5, lane = tid & 31;
    const int gID  = lane >> 2, tig = lane & 3;
    const int jt   = blockIdx.x * 8;
    const int jcol0 = jt + tig * 2;
    const int kw0  = warp * 128;                     // word offset of warp's k-slice
    const int kh0  = warp * 256;                     // half offset of warp's k-slice

    const int a_row  = lane & 15;
    const int a_koff = (lane >> 4) << 3;

    // one-time: weights from g_Br (already [n][k] fp16) -> smem, 16B copies
    for (int idx = tid; idx < 3 * 8 * 128; idx += 128) {
        int row = idx >> 7, c = idx & 127;           // row = g*8+col
        int g = row >> 3, col = row & 7;
        uint4 v = *reinterpret_cast<const uint4*>(
            g_Br + (size_t)(g * 1024 + jt + col) * 1024 + c * 8);
        *reinterpret_cast<uint4*>(Wt + (size_t)row * SMEM_W_STRIDE + c * 8) = v;
    }
    const float bwh0 = whb[jcol0];
    const float bwh1 = whb[jcol0 + 1];

    // register-carried h_prev for this thread's 4 output slots
    float hpv[2][2];
#pragma unroll
    for (int h = 0; h < 2; h++) {
        int r = warp * 16 + gID + h * 8;
        hpv[h][0] = h0[(size_t)r * 1024 + jcol0];
        hpv[h][1] = h0[(size_t)r * 1024 + jcol0 + 1];
    }
    // prefetch XG for t=0
    float xg[2][2][3];
#pragma unroll
    for (int h = 0; h < 2; h++) {
        int r = warp * 16 + gID + h * 8;
        const float* xr = g_XG + (size_t)r * 3072 + jcol0;
#pragma unroll
        for (int cc = 0; cc < 2; cc++) {
            xg[h][cc][0] = xr[cc];
            xg[h][cc][1] = xr[1024 + cc];
            xg[h][cc][2] = xr[2048 + cc];
        }
    }
    __syncthreads();

    float* Red = reinterpret_cast<float*>(Hs);       // [src4][mt4][g3][lane32][4]

    for (int t = 0; t < 512; t++) {
        const __half* hsrc = g_h + (size_t)(t & 1) * 65536;
        __half*       hdst = g_h + (size_t)((t + 1) & 1) * 65536;

        // ---- per-warp chunked h staging: 4 groups of (64 rows x 64 halves)
#pragma unroll
        for (int q = 0; q < 4; q++) {
#pragma unroll
            for (int i = lane; i < 512; i += 32) {
                int r = i >> 3, cc = i & 7;
                cp_async16(Hs + (size_t)r * SMEM_H_STRIDE + kh0 + q * 64 + cc * 8,
                           hsrc + (size_t)r * 1024 + kh0 + q * 64 + cc * 8);
            }
            cp_commit();
        }

        // ---- k-slice MMA, overlapped with remaining staging groups
        float acc[4][3][4];
#pragma unroll
        for (int mt = 0; mt < 4; mt++)
#pragma unroll
            for (int g = 0; g < 3; g++)
#pragma unroll
                for (int i = 0; i < 4; i++) acc[mt][g][i] = 0.f;

        const uint32_t* Bw = reinterpret_cast<const uint32_t*>(Wt);

        auto do4 = [&](int q) {
#pragma unroll
            for (int kk2 = 0; kk2 < 4; kk2++) {
                int kw = kw0 + (q * 4 + kk2) * 8;          // word offset (k16)
                int kb = kh0 + (q * 4 + kk2) * 16;         // half offset
                uint32_t a[4][4];
#pragma unroll
                for (int mt = 0; mt < 4; mt++)
                    ldsm_x4(a[mt][0], a[mt][1], a[mt][2], a[mt][3],
                            Hs + (mt * 16 + a_row) * SMEM_H_STRIDE + kb + a_koff);
#pragma unroll
                for (int g = 0; g < 3; g++) {
                    uint32_t b0 = Bw[(g * 8 + gID) * (SMEM_W_STRIDE / 2) + kw + tig];
                    uint32_t b1 = Bw[(g * 8 + gID) * (SMEM_W_STRIDE / 2) + kw + tig + 4];
#pragma unroll
                    for (int mt = 0; mt < 4; mt++)
                        mma_f16(acc[mt][g], a[mt][0], a[mt][1], a[mt][2], a[mt][3], b0, b1);
                }
            }
        };
        cp_wait<3>(); do4(0);
        cp_wait<2>(); do4(1);
        cp_wait<1>(); do4(2);
        cp_wait<0>(); do4(3);
        __syncthreads();   // all warps done with Hs before Red overlays it

        // ---- write partial sums to smem
#pragma unroll
        for (int mt = 0; mt < 4; mt++)
#pragma unroll
            for (int g = 0; g < 3; g++) {
                int idx = (((warp * 4 + mt) * 3 + g) * 32 + lane) * 4;
                *reinterpret_cast<float4*>(Red + idx) =
                    make_float4(acc[mt][g][0], acc[mt][g][1], acc[mt][g][2], acc[mt][g][3]);
            }
        __syncthreads();

        // ---- reduce: warp owns m-tile = warp
        float facc[3][4];
#pragma unroll
        for (int g = 0; g < 3; g++)
#pragma unroll
            for (int c = 0; c < 4; c++) facc[g][c] = 0.f;
#pragma unroll
        for (int src = 0; src < 4; src++)
#pragma unroll
            for (int g = 0; g < 3; g++) {
                float4 v = *reinterpret_cast<const float4*>(
                    Red + (((src * 4 + warp) * 3 + g) * 32 + lane) * 4);
                facc[g][0] += v.x; facc[g][1] += v.y;
                facc[g][2] += v.z; facc[g][3] += v.w;
            }

        // ---- fused nonlinearity + stores
#pragma unroll
        for (int h = 0; h < 2; h++) {
            int r = warp * 16 + gID + h * 8;
            float hn[2];
#pragma unroll
            for (int cc = 0; cc < 2; cc++) {
                float g1 = facc[0][h * 2 + cc] + xg[h][cc][0];
                float g2 = facc[1][h * 2 + cc] + xg[h][cc][1];
                float hm = facc[2][h * 2 + cc] + ((cc == 0) ? bwh0 : bwh1);
                float xm = xg[h][cc][2];
                float hs = 1.f / (1.f + __expf(-g1));
                float os = 1.f / (1.f + __expf(-g2));
                float mm = xm + hs * hm;
                hn[cc] = os * hpv[h][cc] + (1.f - os) * tanhf(mm);
                out[((size_t)r * 512 + t) * 1024 + jcol0 + cc] = hn[cc];
                hpv[h][cc] = hn[cc];             // register-carry for next step
            }
            *(reinterpret_cast<__half2*>(hdst + (size_t)r * 1024 + jcol0)) =
                __floats2half2_rn(hn[0], hn[1]);
        }

        // ---- prefetch XG for t+1 (hides DRAM latency behind the barrier)
        if (t + 1 < 512) {
            size_t xb = (size_t)(t + 1) * 64 * 3072;
#pragma unroll
            for (int h = 0; h < 2; h++) {
                int r = warp * 16 + gID + h * 8;
                const float* xr = g_XG + xb + (size_t)r * 3072 + jcol0;
#pragma unroll
                for (int cc = 0; cc < 2; cc++) {
                    xg[h][cc][0] = xr[cc];
                    xg[h][cc][1] = xr[1024 + cc];
                    xg[h][cc][2] = xr[2048 + cc];
                }
            }
        }

        // ---- grid barrier
        __threadfence();
        __syncthreads();
        if (tid == 0) {
            atomicAdd(&g_arrive, 1u);
            unsigned target = (unsigned)(t + 1) * 128u;
            unsigned v;
            do {
                asm volatile("ld.global.acquire.gpu.u32 %0, [%1];"
                             : "=r"(v) : "l"(&g_arrive));
            } while (v < target);
        }
        __syncthreads();
    }
}

extern "C" void kernel_launch(void* const* d_in, const int* in_sizes, int n_in,
                              void* d_out, int out_size) {
    const float* x   = (const float*)d_in[0];
    const float* h0  = (const float*)d_in[1];
    const float* wW  = (const float*)d_in[2];
    const float* wb  = (const float*)d_in[3];
    const float* wxW = (const float*)d_in[4];
    const float* wxb = (const float*)d_in[5];
    const float* whW = (const float*)d_in[6];
    const float* whb = (const float*)d_in[7];
    float* out = (float*)d_out;

    const int smemA = 3 * PA2_STAGE * (int)sizeof(__half);           // 92160 B
    const int smemB = (3 * 8 * SMEM_W_STRIDE + 64 * SMEM_H_STRIDE) * (int)sizeof(__half);
    cudaFuncSetAttribute(phaseA_kernel,
                         cudaFuncAttributeMaxDynamicSharedMemorySize, smemA);
    cudaFuncSetAttribute(phaseB_kernel,
                         cudaFuncAttributeMaxDynamicSharedMemorySize, smemB);

    prep_x_kernel<<<16384, 256>>>(x);
    prep_w_kernel<<<dim3(96, 32, 2), dim3(32, 8)>>>(wW, wxW, whW);
    initB_kernel<<<256, 256>>>(h0);
    phaseA_kernel<<<dim3(12, 256), 512, smemA>>>(wb, wxb);
    phaseB_kernel<<<128, 128, smemB>>>(h0, whb, out);
}